// round 4
// baseline (speedup 1.0000x reference)
#include <cuda_runtime.h>
#include <cstdint>
#include <cstddef>

// ---------------------------------------------------------------------------
// HeteroResonance: out = (0.7*decay + 0.3*softmax(mask(q k^T / 16))) @ hdc
// B=4, T=4096, D=2048, BOT=256
// Strategy: tf32 mma.sync GEMMs with rna-rounded operands (unbiased ~4e-4 err),
// exp-without-max (scores bounded), fused normalize+combine pass.
// ---------------------------------------------------------------------------

namespace {
constexpr int kB   = 4;
constexpr int kT   = 4096;
constexpr int kD   = 2048;
constexpr int kBot = 256;
constexpr int kM1  = kB * kT;  // 16384 rows for projections
}

// Scratch (static device globals -- allocation-free per harness rules)
__device__ float g_hdc_r[(size_t)kB * kT * kD];    // tf32-rounded hdc   (134 MB)
__device__ float g_wq_r[(size_t)kBot * kD];        // tf32-rounded Wq
__device__ float g_wk_r[(size_t)kBot * kD];        // tf32-rounded Wk
__device__ float g_q[(size_t)kM1 * kBot];          // q projections (tf32-rounded)
__device__ float g_k[(size_t)kM1 * kBot];          // k projections (tf32-rounded)
__device__ float g_s[(size_t)kB * kT * kT];        // p / combined   (268 MB)

// ---------------------------------------------------------------------------
// helpers
// ---------------------------------------------------------------------------
__device__ __forceinline__ uint32_t f2tf(float x) {
    uint32_t r;
    asm("cvt.rna.tf32.f32 %0, %1;" : "=r"(r) : "f"(x));
    return r;
}
__device__ __forceinline__ float tfround(float x) { return __uint_as_float(f2tf(x)); }

__device__ __forceinline__ void cpa16(uint32_t saddr, const void* gaddr) {
    asm volatile("cp.async.cg.shared.global [%0], [%1], 16;" :: "r"(saddr), "l"(gaddr));
}
__device__ __forceinline__ void cp_commit() { asm volatile("cp.async.commit_group;"); }
__device__ __forceinline__ void cp_wait1()  { asm volatile("cp.async.wait_group 1;"); }
__device__ __forceinline__ void cp_wait0()  { asm volatile("cp.async.wait_group 0;"); }

__device__ __forceinline__ void mma8(float c[4], const uint32_t a[4], const uint32_t b[2]) {
    asm volatile(
        "mma.sync.aligned.m16n8k8.row.col.f32.tf32.tf32.f32 "
        "{%0,%1,%2,%3},{%4,%5,%6,%7},{%8,%9},{%0,%1,%2,%3};"
        : "+f"(c[0]), "+f"(c[1]), "+f"(c[2]), "+f"(c[3])
        : "r"(a[0]), "r"(a[1]), "r"(a[2]), "r"(a[3]), "r"(b[0]), "r"(b[1]));
}

// ---------------------------------------------------------------------------
// K0: round fp32 -> tf32 (rna) into scratch. which: 0=hdc, 1=Wq, 2=Wk
// ---------------------------------------------------------------------------
__global__ void k_round(const float* __restrict__ src, int n, int which) {
    float* dst = (which == 0) ? g_hdc_r : (which == 1) ? g_wq_r : g_wk_r;
    int i = blockIdx.x * blockDim.x + threadIdx.x;
    int stride = gridDim.x * blockDim.x;
    for (; i < n; i += stride) dst[i] = tfround(src[i]);
}

// ---------------------------------------------------------------------------
// K1: projections. C[M,N] = A[M,K] @ W[N,K]^T + bias, tf32-rounded store.
// A = g_hdc_r (M=16384, K=2048), W = g_wq_r / g_wk_r (N=256), C = g_q / g_k.
// Both smem tiles stored [row][k] with ld=20 (conflict-free fragment LDS).
// ---------------------------------------------------------------------------
__global__ __launch_bounds__(256)
void k_proj(const float* __restrict__ bias, int which) {
    __shared__ uint32_t As[2][128][20];
    __shared__ uint32_t Bs[2][128][20];
    const float* A  = g_hdc_r;
    const float* Bw = which ? g_wk_r : g_wq_r;
    float*       C  = which ? g_k : g_q;
    const int K = kD, N = kBot;

    const int tid = threadIdx.x;
    const int lane = tid & 31, warp = tid >> 5;
    const int g = lane >> 2, t = lane & 3;
    const int wm = warp >> 2, wn = warp & 3;        // 2 x 4 warps, 64x32 each
    const int m0 = blockIdx.y * 128, n0 = blockIdx.x * 128;

    float acc[4][4][4];
#pragma unroll
    for (int a = 0; a < 4; a++)
#pragma unroll
        for (int b = 0; b < 4; b++)
#pragma unroll
            for (int c = 0; c < 4; c++) acc[a][b][c] = 0.f;

    const uint32_t sA = (uint32_t)__cvta_generic_to_shared(&As[0][0][0]);
    const uint32_t sB = (uint32_t)__cvta_generic_to_shared(&Bs[0][0][0]);
    const int r_ld = tid >> 2;           // 0..63
    const int c_ld = (tid & 3) << 2;     // 0,4,8,12

    auto issue = [&](int buf, int k0) {
#pragma unroll
        for (int i = 0; i < 2; i++) {
            int row = r_ld + i * 64;
            uint32_t off = (uint32_t)((buf * 128 * 20 + row * 20 + c_ld) << 2);
            cpa16(sA + off, A  + (size_t)(m0 + row) * K + k0 + c_ld);
            cpa16(sB + off, Bw + (size_t)(n0 + row) * K + k0 + c_ld);
        }
        cp_commit();
    };

    const int nt = K / 16;
    issue(0, 0);
    for (int tk = 0; tk < nt; ++tk) {
        if (tk + 1 < nt) { issue((tk + 1) & 1, (tk + 1) * 16); cp_wait1(); }
        else             { cp_wait0(); }
        __syncthreads();
        const uint32_t (*At)[20] = As[tk & 1];
        const uint32_t (*Bt)[20] = Bs[tk & 1];
#pragma unroll
        for (int ks = 0; ks < 2; ++ks) {
            uint32_t af[4][4], bf[4][2];
            const int kc = ks * 8 + t;
#pragma unroll
            for (int mi = 0; mi < 4; ++mi) {
                int rb = wm * 64 + mi * 16;
                af[mi][0] = At[rb + g][kc];
                af[mi][1] = At[rb + g + 8][kc];
                af[mi][2] = At[rb + g][kc + 4];
                af[mi][3] = At[rb + g + 8][kc + 4];
            }
#pragma unroll
            for (int ni = 0; ni < 4; ++ni) {
                int cb = wn * 32 + ni * 8 + g;
                bf[ni][0] = Bt[cb][kc];
                bf[ni][1] = Bt[cb][kc + 4];
            }
#pragma unroll
            for (int mi = 0; mi < 4; ++mi)
#pragma unroll
                for (int ni = 0; ni < 4; ++ni) mma8(acc[mi][ni], af[mi], bf[ni]);
        }
        __syncthreads();
    }
#pragma unroll
    for (int mi = 0; mi < 4; ++mi) {
        int r0 = m0 + wm * 64 + mi * 16 + g;
#pragma unroll
        for (int ni = 0; ni < 4; ++ni) {
            int c0 = n0 + wn * 32 + ni * 8 + 2 * t;
#pragma unroll
            for (int r = 0; r < 4; ++r) {
                int row = r0 + ((r & 2) ? 8 : 0);
                int col = c0 + (r & 1);
                C[(size_t)row * N + col] = tfround(acc[mi][ni][r] + bias[col]);
            }
        }
    }
}

// ---------------------------------------------------------------------------
// K2: masked exp-scores. p[i,j] = (j <= i-4) ? exp(q_i . k_j / 16) : 0
// per-batch GEMM M=N=4096, K=256. Stores fp32 p into g_s (no rounding needed).
// ---------------------------------------------------------------------------
__global__ __launch_bounds__(256)
void k_scores() {
    __shared__ uint32_t As[2][128][20];
    __shared__ uint32_t Bs[2][128][20];
    const int bz = blockIdx.z;
    const float* A  = g_q + (size_t)bz * kT * kBot;
    const float* Bw = g_k + (size_t)bz * kT * kBot;
    float*       C  = g_s + (size_t)bz * kT * kT;
    const int K = kBot;

    const int tid = threadIdx.x;
    const int lane = tid & 31, warp = tid >> 5;
    const int g = lane >> 2, t = lane & 3;
    const int wm = warp >> 2, wn = warp & 3;
    const int m0 = blockIdx.y * 128, n0 = blockIdx.x * 128;

    float acc[4][4][4];
#pragma unroll
    for (int a = 0; a < 4; a++)
#pragma unroll
        for (int b = 0; b < 4; b++)
#pragma unroll
            for (int c = 0; c < 4; c++) acc[a][b][c] = 0.f;

    const uint32_t sA = (uint32_t)__cvta_generic_to_shared(&As[0][0][0]);
    const uint32_t sB = (uint32_t)__cvta_generic_to_shared(&Bs[0][0][0]);
    const int r_ld = tid >> 2;
    const int c_ld = (tid & 3) << 2;

    auto issue = [&](int buf, int k0) {
#pragma unroll
        for (int i = 0; i < 2; i++) {
            int row = r_ld + i * 64;
            uint32_t off = (uint32_t)((buf * 128 * 20 + row * 20 + c_ld) << 2);
            cpa16(sA + off, A  + (size_t)(m0 + row) * K + k0 + c_ld);
            cpa16(sB + off, Bw + (size_t)(n0 + row) * K + k0 + c_ld);
        }
        cp_commit();
    };

    const int nt = K / 16;  // 16
    issue(0, 0);
    for (int tk = 0; tk < nt; ++tk) {
        if (tk + 1 < nt) { issue((tk + 1) & 1, (tk + 1) * 16); cp_wait1(); }
        else             { cp_wait0(); }
        __syncthreads();
        const uint32_t (*At)[20] = As[tk & 1];
        const uint32_t (*Bt)[20] = Bs[tk & 1];
#pragma unroll
        for (int ks = 0; ks < 2; ++ks) {
            uint32_t af[4][4], bf[4][2];
            const int kc = ks * 8 + t;
#pragma unroll
            for (int mi = 0; mi < 4; ++mi) {
                int rb = wm * 64 + mi * 16;
                af[mi][0] = At[rb + g][kc];
                af[mi][1] = At[rb + g + 8][kc];
                af[mi][2] = At[rb + g][kc + 4];
                af[mi][3] = At[rb + g + 8][kc + 4];
            }
#pragma unroll
            for (int ni = 0; ni < 4; ++ni) {
                int cb = wn * 32 + ni * 8 + g;
                bf[ni][0] = Bt[cb][kc];
                bf[ni][1] = Bt[cb][kc + 4];
            }
#pragma unroll
            for (int mi = 0; mi < 4; ++mi)
#pragma unroll
                for (int ni = 0; ni < 4; ++ni) mma8(acc[mi][ni], af[mi], bf[ni]);
        }
        __syncthreads();
    }
#pragma unroll
    for (int mi = 0; mi < 4; ++mi) {
        int r0 = m0 + wm * 64 + mi * 16 + g;
#pragma unroll
        for (int ni = 0; ni < 4; ++ni) {
            int c0 = n0 + wn * 32 + ni * 8 + 2 * t;
#pragma unroll
            for (int r = 0; r < 4; ++r) {
                int i = r0 + ((r & 2) ? 8 : 0);
                int j = c0 + (r & 1);
                float p = (j <= i - 4) ? __expf(acc[mi][ni][r] * 0.0625f) : 0.f;
                C[(size_t)i * kT + j] = p;
            }
        }
    }
}

// ---------------------------------------------------------------------------
// K3: per row: l = sum_j p; combined = 0.7*decay + 0.3*p/l (l==0 -> uniform
// 1/T, matching jax softmax of an all-masked row). tf32-rounded in-place.
// ---------------------------------------------------------------------------
__global__ __launch_bounds__(256)
void k_combine(const float* __restrict__ decay) {
    __shared__ float sp[kT];
    __shared__ float red[256];
    const int r  = blockIdx.x;       // global row 0..16383
    const int bz = r >> 12;
    const int i  = r & (kT - 1);
    float*       srow = g_s   + (size_t)bz * kT * kT + (size_t)i * kT;
    const float* drow = decay + (size_t)bz * kT * kT + (size_t)i * kT;
    const int tid = threadIdx.x;

    float lsum = 0.f;
    for (int j = tid * 4; j < kT; j += 1024) {
        float4 v = *reinterpret_cast<const float4*>(srow + j);
        *reinterpret_cast<float4*>(sp + j) = v;
        lsum += v.x + v.y + v.z + v.w;
    }
    red[tid] = lsum;
    __syncthreads();
    for (int s = 128; s > 0; s >>= 1) {
        if (tid < s) red[tid] += red[tid + s];
        __syncthreads();
    }
    const float l    = red[0];
    const float invl = (l > 0.f) ? (0.3f / l) : 0.f;
    const float base = (l > 0.f) ? 0.f : (0.3f / (float)kT);

    for (int j = tid * 4; j < kT; j += 1024) {
        float4 d = *reinterpret_cast<const float4*>(drow + j);
        float4 p = *reinterpret_cast<const float4*>(sp + j);
        float4 o;
        o.x = tfround(0.7f * d.x + invl * p.x + base);
        o.y = tfround(0.7f * d.y + invl * p.y + base);
        o.z = tfround(0.7f * d.z + invl * p.z + base);
        o.w = tfround(0.7f * d.w + invl * p.w + base);
        *reinterpret_cast<float4*>(srow + j) = o;
    }
}

// ---------------------------------------------------------------------------
// K4: out = combined @ hdc (per batch). A = g_s [4096,4096] rm, B = g_hdc_r
// [4096,2048] rm (K x N, n-contiguous -> smem [k][n] ld=136). 275 GFLOP.
// ---------------------------------------------------------------------------
__global__ __launch_bounds__(256)
void k_out(float* __restrict__ Out) {
    __shared__ uint32_t As[2][128][20];
    __shared__ uint32_t Bs[2][16][136];
    const int bz = blockIdx.z;
    const float* A  = g_s     + (size_t)bz * kT * kT;
    const float* Bg = g_hdc_r + (size_t)bz * kT * kD;
    float*       C  = Out     + (size_t)bz * kT * kD;
    const int K = kT;

    const int tid = threadIdx.x;
    const int lane = tid & 31, warp = tid >> 5;
    const int g = lane >> 2, t = lane & 3;
    const int wm = warp >> 2, wn = warp & 3;
    const int m0 = blockIdx.y * 128, n0 = blockIdx.x * 128;

    float acc[4][4][4];
#pragma unroll
    for (int a = 0; a < 4; a++)
#pragma unroll
        for (int b = 0; b < 4; b++)
#pragma unroll
            for (int c = 0; c < 4; c++) acc[a][b][c] = 0.f;

    const uint32_t sA = (uint32_t)__cvta_generic_to_shared(&As[0][0][0]);
    const uint32_t sB = (uint32_t)__cvta_generic_to_shared(&Bs[0][0][0]);
    const int rA = tid >> 2;             // 0..63
    const int cA = (tid & 3) << 2;       // 0,4,8,12
    const int rB = tid >> 5;             // 0..7
    const int cB = (tid & 31) << 2;      // 0..124

    auto issue = [&](int buf, int k0) {
#pragma unroll
        for (int i = 0; i < 2; i++) {
            int row = rA + i * 64;
            uint32_t offA = (uint32_t)((buf * 128 * 20 + row * 20 + cA) << 2);
            cpa16(sA + offA, A + (size_t)(m0 + row) * K + k0 + cA);
            int krow = rB + i * 8;
            uint32_t offB = (uint32_t)((buf * 16 * 136 + krow * 136 + cB) << 2);
            cpa16(sB + offB, Bg + (size_t)(k0 + krow) * kD + n0 + cB);
        }
        cp_commit();
    };

    const int nt = K / 16;  // 256
    issue(0, 0);
    for (int tk = 0; tk < nt; ++tk) {
        if (tk + 1 < nt) { issue((tk + 1) & 1, (tk + 1) * 16); cp_wait1(); }
        else             { cp_wait0(); }
        __syncthreads();
        const uint32_t (*At)[20]  = As[tk & 1];
        const uint32_t (*Bt)[136] = Bs[tk & 1];
#pragma unroll
        for (int ks = 0; ks < 2; ++ks) {
            uint32_t af[4][4], bf[4][2];
            const int kc = ks * 8 + t;
#pragma unroll
            for (int mi = 0; mi < 4; ++mi) {
                int rb = wm * 64 + mi * 16;
                af[mi][0] = At[rb + g][kc];
                af[mi][1] = At[rb + g + 8][kc];
                af[mi][2] = At[rb + g][kc + 4];
                af[mi][3] = At[rb + g + 8][kc + 4];
            }
#pragma unroll
            for (int ni = 0; ni < 4; ++ni) {
                int cb = wn * 32 + ni * 8 + g;
                bf[ni][0] = Bt[kc][cb];
                bf[ni][1] = Bt[kc + 4][cb];
            }
#pragma unroll
            for (int mi = 0; mi < 4; ++mi)
#pragma unroll
                for (int ni = 0; ni < 4; ++ni) mma8(acc[mi][ni], af[mi], bf[ni]);
        }
        __syncthreads();
    }
#pragma unroll
    for (int mi = 0; mi < 4; ++mi) {
        int r0 = m0 + wm * 64 + mi * 16 + g;
#pragma unroll
        for (int ni = 0; ni < 4; ++ni) {
            int c0 = n0 + wn * 32 + ni * 8 + 2 * t;
#pragma unroll
            for (int r = 0; r < 4; ++r) {
                int row = r0 + ((r & 2) ? 8 : 0);
                int col = c0 + (r & 1);
                C[(size_t)row * kD + col] = acc[mi][ni][r];
            }
        }
    }
}

// ---------------------------------------------------------------------------
// launch
// ---------------------------------------------------------------------------
extern "C" void kernel_launch(void* const* d_in, const int* in_sizes, int n_in,
                              void* d_out, int out_size) {
    (void)in_sizes; (void)n_in; (void)out_size;
    const float* hdc   = (const float*)d_in[0];
    const float* decay = (const float*)d_in[1];
    const float* Wq    = (const float*)d_in[2];
    const float* bq    = (const float*)d_in[3];
    const float* Wk    = (const float*)d_in[4];
    const float* bk    = (const float*)d_in[5];
    float* out = (float*)d_out;

    k_round<<<8192, 256>>>(hdc, kB * kT * kD, 0);
    k_round<<<512, 256>>>(Wq, kBot * kD, 1);
    k_round<<<512, 256>>>(Wk, kBot * kD, 2);

    k_proj<<<dim3(kBot / 128, kM1 / 128), 256>>>(bq, 0);
    k_proj<<<dim3(kBot / 128, kM1 / 128), 256>>>(bk, 1);

    k_scores<<<dim3(kT / 128, kT / 128, kB), 256>>>();

    k_combine<<<kM1, 256>>>(decay);

    k_out<<<dim3(kD / 128, kT / 128, kB), 256>>>(out);
}

// round 9
// speedup vs baseline: 1.0858x; 1.0858x over previous
#include <cuda_runtime.h>
#include <cstdint>
#include <cstddef>

// ---------------------------------------------------------------------------
// HeteroResonance: out = (0.7*decay + 0.3*softmax(mask(q k^T / 16))) @ hdc
// B=4, T=4096, D=2048, BOT=256
// R8: legacy mma.sync tf32 only (harness PTX target is plain sm_103 -- no
// tcgen05). Unified 128x256-tile GEMM, 64x64 warp tiles, 3-stage cp.async.
// ---------------------------------------------------------------------------

namespace {
constexpr int kB   = 4;
constexpr int kT   = 4096;
constexpr int kD   = 2048;
constexpr int kBot = 256;
constexpr int kM1  = kB * kT;

constexpr int TM = 128;      // CTA tile M
constexpr int TN = 256;      // CTA tile N
constexpr int TK = 16;       // k-tile
constexpr int NS = 3;        // pipeline stages

constexpr int A_LD  = 20;                      // padded floats per A row
constexpr int A_SZ  = TM * A_LD;               // floats per A stage (2560)
constexpr int BN_LD = 20;                      // B n-major row pad
constexpr int BN_SZ = TN * BN_LD;              // 5120 floats
constexpr int BK_LD = 264;                     // B k-major row pad (256+8)
constexpr int BK_SZ = TK * BK_LD;              // 4224 floats
}

// Scratch (static device globals -- allocation-free per harness rules)
__device__ __align__(256) float g_hdc_r[(size_t)kB * kT * kD];  // rounded hdc
__device__ __align__(256) float g_wq_r[(size_t)kBot * kD];
__device__ __align__(256) float g_wk_r[(size_t)kBot * kD];
__device__ __align__(256) float g_q[(size_t)kM1 * kBot];
__device__ __align__(256) float g_k[(size_t)kM1 * kBot];
__device__ __align__(256) float g_s[(size_t)kB * kT * kT];      // p / combined

// ---------------------------------------------------------------------------
// helpers
// ---------------------------------------------------------------------------
__device__ __forceinline__ uint32_t f2tf(float x) {
    uint32_t r;
    asm("cvt.rna.tf32.f32 %0, %1;" : "=r"(r) : "f"(x));
    return r;
}
__device__ __forceinline__ float tfround(float x) { return __uint_as_float(f2tf(x)); }

__device__ __forceinline__ void cpa16(uint32_t saddr, const void* gaddr) {
    asm volatile("cp.async.cg.shared.global [%0], [%1], 16;" :: "r"(saddr), "l"(gaddr));
}
__device__ __forceinline__ void cp_commit() { asm volatile("cp.async.commit_group;"); }
template <int N>
__device__ __forceinline__ void cp_waitg() { asm volatile("cp.async.wait_group %0;" :: "n"(N)); }

__device__ __forceinline__ void mma8(float c[4], const uint32_t a[4], const uint32_t b[2]) {
    asm volatile(
        "mma.sync.aligned.m16n8k8.row.col.f32.tf32.tf32.f32 "
        "{%0,%1,%2,%3},{%4,%5,%6,%7},{%8,%9},{%0,%1,%2,%3};"
        : "+f"(c[0]), "+f"(c[1]), "+f"(c[2]), "+f"(c[3])
        : "r"(a[0]), "r"(a[1]), "r"(a[2]), "r"(a[3]), "r"(b[0]), "r"(b[1]));
}

// ---------------------------------------------------------------------------
// K0: round fp32 -> tf32 (rna). which: 0=hdc, 1=Wq, 2=Wk
// ---------------------------------------------------------------------------
__global__ void k_round(const float* __restrict__ src, int n, int which) {
    float* dst = (which == 0) ? g_hdc_r : (which == 1) ? g_wq_r : g_wk_r;
    int i = blockIdx.x * blockDim.x + threadIdx.x;
    int stride = gridDim.x * blockDim.x;
    for (; i < n; i += stride) dst[i] = tfround(src[i]);
}

// ---------------------------------------------------------------------------
// Unified tf32 GEMM, CTA tile 128x256, warp tile 64x64 (2x4 warps), 3-stage
// cp.async ring.
// MODE 0: proj   C = A @ W^T + bias (tfround). A=g_hdc_r, B n-major (W).
// MODE 1: scores C = exp(mask(A @ B^T / 16)). A=g_q, B=g_k n-major. skip-tiles.
// MODE 2: out    C = A @ B.  A=g_s, B=g_hdc_r in [k][n] layout.
// ---------------------------------------------------------------------------
template <int MODE>
__global__ __launch_bounds__(256)
void k_gemm(const float* __restrict__ bias, float* __restrict__ outp, int which) {
    extern __shared__ float sm[];
    const int bz = blockIdx.z;
    const int m0 = blockIdx.y * TM, n0 = blockIdx.x * TN;
    const int tid = threadIdx.x;
    const int lane = tid & 31, warp = tid >> 5;
    const int g = lane >> 2, t = lane & 3;
    const int wm = warp >> 2, wn = warp & 3;    // 2 x 4 warps; warp tile 64x64

    const float* A;
    const float* Bm;
    float* C;
    int Kdim, lda, ldb, ldc;
    if (MODE == 0) {
        A   = g_hdc_r;                       lda = kD;
        Bm  = which ? g_wk_r : g_wq_r;       ldb = kD;
        C   = which ? g_k : g_q;             ldc = kBot;
        Kdim = kD;
    } else if (MODE == 1) {
        A   = g_q + (size_t)bz * kT * kBot;  lda = kBot;
        Bm  = g_k + (size_t)bz * kT * kBot;  ldb = kBot;
        C   = g_s + (size_t)bz * kT * kT;    ldc = kT;
        Kdim = kBot;
    } else {
        A   = g_s + (size_t)bz * kT * kT;    lda = kT;
        Bm  = g_hdc_r + (size_t)bz * kT * kD; ldb = kD;   // [k][n]
        C   = outp + (size_t)bz * kT * kD;   ldc = kD;
        Kdim = kT;
    }

    // Fully-masked scores tile: store zeros, skip compute.
    if (MODE == 1 && n0 >= m0 + 124) {
        for (int i = tid * 4; i < TM * TN; i += 256 * 4) {
            int r = i / TN, c = i % TN;
            *reinterpret_cast<float4*>(&C[(size_t)(m0 + r) * ldc + n0 + c]) =
                make_float4(0.f, 0.f, 0.f, 0.f);
        }
        return;
    }

    constexpr int B_SZ = (MODE == 2) ? BK_SZ : BN_SZ;
    constexpr int STG  = A_SZ + B_SZ;
    const uint32_t sbase = (uint32_t)__cvta_generic_to_shared(sm);

    float acc[4][8][4];
#pragma unroll
    for (int a = 0; a < 4; a++)
#pragma unroll
        for (int b = 0; b < 8; b++)
#pragma unroll
            for (int c = 0; c < 4; c++) acc[a][b][c] = 0.f;

    auto load_tile = [&](int L, int s) {
        const int k0 = L * TK;
        const uint32_t aoff = sbase + (uint32_t)(s * STG) * 4u;
        const uint32_t boff = aoff + (uint32_t)A_SZ * 4u;
        // A: 128 rows x 16k = 512 16B-chunks, 2 per thread
#pragma unroll
        for (int i = 0; i < 2; ++i) {
            int id = tid + i * 256;
            int r = id >> 2, c = (id & 3) << 2;
            cpa16(aoff + (uint32_t)(r * A_LD + c) * 4u,
                  A + (size_t)(m0 + r) * lda + k0 + c);
        }
        if (MODE == 2) {
            // B [k][n]: 16 k-rows x 256 n = 1024 chunks, 4 per thread
#pragma unroll
            for (int i = 0; i < 4; ++i) {
                int id = tid + i * 256;
                int r = id >> 6, c = (id & 63) << 2;
                cpa16(boff + (uint32_t)(r * BK_LD + c) * 4u,
                      Bm + (size_t)(k0 + r) * ldb + n0 + c);
            }
        } else {
            // B n-major: 256 rows x 16k = 1024 chunks, 4 per thread
#pragma unroll
            for (int i = 0; i < 4; ++i) {
                int id = tid + i * 256;
                int r = id >> 2, c = (id & 3) << 2;
                cpa16(boff + (uint32_t)(r * BN_LD + c) * 4u,
                      Bm + (size_t)(n0 + r) * ldb + k0 + c);
            }
        }
        cp_commit();
    };

    const int nt = Kdim / TK;
    load_tile(0, 0);
    if (nt > 1) load_tile(1, 1);

    for (int tk = 0; tk < nt; ++tk) {
        const int s = tk % NS;
        if (tk + NS - 1 < nt) cp_waitg<NS - 2>(); else cp_waitg<0>();
        __syncthreads();
        // prefetch next stage into the buffer freed last iteration
        if (tk + NS - 1 < nt) load_tile(tk + NS - 1, (tk + NS - 1) % NS);

        const uint32_t* At = reinterpret_cast<const uint32_t*>(sm + s * STG);
        const uint32_t* Bt = reinterpret_cast<const uint32_t*>(sm + s * STG + A_SZ);
#pragma unroll
        for (int ks = 0; ks < 2; ++ks) {
            const int kc = ks * 8 + t;
            uint32_t af[4][4], bf[8][2];
#pragma unroll
            for (int mi = 0; mi < 4; ++mi) {
                int rb = wm * 64 + mi * 16;
                af[mi][0] = At[(rb + g) * A_LD + kc];
                af[mi][1] = At[(rb + g + 8) * A_LD + kc];
                af[mi][2] = At[(rb + g) * A_LD + kc + 4];
                af[mi][3] = At[(rb + g + 8) * A_LD + kc + 4];
            }
#pragma unroll
            for (int ni = 0; ni < 8; ++ni) {
                int cb = wn * 64 + ni * 8 + g;
                if (MODE == 2) {
                    bf[ni][0] = Bt[kc * BK_LD + cb];
                    bf[ni][1] = Bt[(kc + 4) * BK_LD + cb];
                } else {
                    bf[ni][0] = Bt[cb * BN_LD + kc];
                    bf[ni][1] = Bt[cb * BN_LD + kc + 4];
                }
            }
#pragma unroll
            for (int mi = 0; mi < 4; ++mi)
#pragma unroll
                for (int ni = 0; ni < 8; ++ni) mma8(acc[mi][ni], af[mi], bf[ni]);
        }
        __syncthreads();
    }

    // epilogue
#pragma unroll
    for (int mi = 0; mi < 4; ++mi) {
        const int r0 = m0 + wm * 64 + mi * 16 + g;
#pragma unroll
        for (int ni = 0; ni < 8; ++ni) {
            const int col = n0 + wn * 64 + ni * 8 + 2 * t;
#pragma unroll
            for (int h = 0; h < 2; ++h) {       // h=0: rows r0, h=1: r0+8
                const int row = r0 + h * 8;
                float v0 = acc[mi][ni][h * 2 + 0];
                float v1 = acc[mi][ni][h * 2 + 1];
                float2 o;
                if (MODE == 0) {
                    o.x = tfround(v0 + bias[col]);
                    o.y = tfround(v1 + bias[col + 1]);
                } else if (MODE == 1) {
                    o.x = (col     <= row - 4) ? __expf(v0 * 0.0625f) : 0.f;
                    o.y = (col + 1 <= row - 4) ? __expf(v1 * 0.0625f) : 0.f;
                } else {
                    o.x = v0;
                    o.y = v1;
                }
                *reinterpret_cast<float2*>(&C[(size_t)row * ldc + col]) = o;
            }
        }
    }
}

// ---------------------------------------------------------------------------
// K3: per row: l = sum_j p; combined = 0.7*decay + 0.3*p/l (l==0 -> 1/T),
// tf32-rounded in-place.
// ---------------------------------------------------------------------------
__global__ __launch_bounds__(256)
void k_combine(const float* __restrict__ decay) {
    __shared__ float sp[kT];
    __shared__ float red[256];
    const int r  = blockIdx.x;
    const int bz = r >> 12;
    const int i  = r & (kT - 1);
    float*       srow = g_s   + (size_t)bz * kT * kT + (size_t)i * kT;
    const float* drow = decay + (size_t)bz * kT * kT + (size_t)i * kT;
    const int tid = threadIdx.x;

    float lsum = 0.f;
    for (int j = tid * 4; j < kT; j += 1024) {
        float4 v = *reinterpret_cast<const float4*>(srow + j);
        *reinterpret_cast<float4*>(sp + j) = v;
        lsum += v.x + v.y + v.z + v.w;
    }
    red[tid] = lsum;
    __syncthreads();
    for (int s = 128; s > 0; s >>= 1) {
        if (tid < s) red[tid] += red[tid + s];
        __syncthreads();
    }
    const float l    = red[0];
    const float invl = (l > 0.f) ? (0.3f / l) : 0.f;
    const float base = (l > 0.f) ? 0.f : (0.3f / (float)kT);

    for (int j = tid * 4; j < kT; j += 1024) {
        float4 d = *reinterpret_cast<const float4*>(drow + j);
        float4 p = *reinterpret_cast<const float4*>(sp + j);
        float4 o;
        o.x = tfround(0.7f * d.x + invl * p.x + base);
        o.y = tfround(0.7f * d.y + invl * p.y + base);
        o.z = tfround(0.7f * d.z + invl * p.z + base);
        o.w = tfround(0.7f * d.w + invl * p.w + base);
        *reinterpret_cast<float4*>(srow + j) = o;
    }
}

// ---------------------------------------------------------------------------
// launch
// ---------------------------------------------------------------------------
namespace {
constexpr int SMEM_N = NS * (A_SZ + BN_SZ) * 4;  // proj/scores stages (92160 B)
constexpr int SMEM_K = NS * (A_SZ + BK_SZ) * 4;  // out stages        (81408 B)
}

extern "C" void kernel_launch(void* const* d_in, const int* in_sizes, int n_in,
                              void* d_out, int out_size) {
    (void)in_sizes; (void)n_in; (void)out_size;
    const float* hdc   = (const float*)d_in[0];
    const float* decay = (const float*)d_in[1];
    const float* Wq    = (const float*)d_in[2];
    const float* bq    = (const float*)d_in[3];
    const float* Wk    = (const float*)d_in[4];
    const float* bk    = (const float*)d_in[5];
    float* out = (float*)d_out;

    static bool attr_done = false;
    if (!attr_done) {
        cudaFuncSetAttribute(k_gemm<0>, cudaFuncAttributeMaxDynamicSharedMemorySize, SMEM_N);
        cudaFuncSetAttribute(k_gemm<1>, cudaFuncAttributeMaxDynamicSharedMemorySize, SMEM_N);
        cudaFuncSetAttribute(k_gemm<2>, cudaFuncAttributeMaxDynamicSharedMemorySize, SMEM_K);
        attr_done = true;
    }

    k_round<<<8192, 256>>>(hdc, kB * kT * kD, 0);
    k_round<<<512, 256>>>(Wq, kBot * kD, 1);
    k_round<<<512, 256>>>(Wk, kBot * kD, 2);

    // projections: C[16384,256] = hdc @ W^T + b
    k_gemm<0><<<dim3(kBot / TN, kM1 / TM, 1), 256, SMEM_N>>>(bq, nullptr, 0);
    k_gemm<0><<<dim3(kBot / TN, kM1 / TM, 1), 256, SMEM_N>>>(bk, nullptr, 1);

    // scores -> p
    k_gemm<1><<<dim3(kT / TN, kT / TM, kB), 256, SMEM_N>>>(nullptr, nullptr, 0);

    k_combine<<<kM1, 256>>>(decay);

    // out = combined @ hdc
    k_gemm<2><<<dim3(kD / TN, kT / TM, kB), 256, SMEM_K>>>(nullptr, out, 0);
}